// round 6
// baseline (speedup 1.0000x reference)
#include <cuda_runtime.h>
#include <cstdint>

#define Hdim 256
#define Sdim 512
#define Bdim 256
#define G3   768

// 402 MB scratch for precomputed input-gate activations gi[b*S + t][768]
__device__ float g_gi[(size_t)Bdim * Sdim * G3];

// ---- f32x2 helpers ---------------------------------------------------------
typedef unsigned long long u64;
__device__ __forceinline__ u64 pack2(float lo, float hi) {
    u64 r; asm("mov.b64 %0,{%1,%2};" : "=l"(r) : "f"(lo), "f"(hi)); return r;
}
__device__ __forceinline__ void unpack2(u64 v, float& lo, float& hi) {
    asm("mov.b64 {%0,%1},%2;" : "=f"(lo), "=f"(hi) : "l"(v));
}
__device__ __forceinline__ u64 ffma2(u64 a, u64 b, u64 c) {
    u64 d; asm("fma.rn.f32x2 %0,%1,%2,%3;" : "=l"(d) : "l"(a), "l"(b), "l"(c));
    return d;
}

// ---------------------------------------------------------------------------
// Kernel 1: gi = x @ W_ih^T + b_ih (v1 — measured ~1.44 ms, at f32 roofline).
// ---------------------------------------------------------------------------
__global__ __launch_bounds__(256) void gi_gemm_kernel(const float* __restrict__ seq,
                                                      const float* __restrict__ W_ih,
                                                      const float* __restrict__ b_ih) {
    __shared__ float As[32 * 128];
    __shared__ float Ws[32 * 132];
    const int tid = threadIdx.x;
    const int b   = blockIdx.x >> 2;
    const int t0  = (blockIdx.x & 3) * 128;
    const int n0  = blockIdx.y * 128;
    const float* seqb = seq + (size_t)b * (Hdim * Sdim);

    const int tm = (tid & 15) * 4;
    const int tn = (tid >> 4) * 4;
    const int lane = tid & 31, wp = tid >> 5;

    float acc[8][8];
#pragma unroll
    for (int i = 0; i < 8; ++i)
#pragma unroll
        for (int j = 0; j < 8; ++j) acc[i][j] = 0.f;

    for (int kt = 0; kt < 8; ++kt) {
        int pos = tid;
#pragma unroll
        for (int i = 0; i < 4; ++i, pos += 256) {
            int k  = pos >> 5;
            int mq = (pos & 31) << 2;
            float4 v = *(const float4*)(seqb + (size_t)(kt * 32 + k) * Sdim + t0 + mq);
            *(float4*)&As[k * 128 + mq] = v;
        }
#pragma unroll
        for (int i = 0; i < 16; ++i) {
            int n = wp * 16 + i;
            Ws[lane * 132 + n] = W_ih[(size_t)(n0 + n) * Hdim + kt * 32 + lane];
        }
        __syncthreads();
#pragma unroll
        for (int kk = 0; kk < 32; ++kk) {
            float4 a0 = *(const float4*)&As[kk * 128 + tm];
            float4 a1 = *(const float4*)&As[kk * 128 + tm + 64];
            float4 w0 = *(const float4*)&Ws[kk * 132 + tn];
            float4 w1 = *(const float4*)&Ws[kk * 132 + tn + 64];
            float am[8] = {a0.x, a0.y, a0.z, a0.w, a1.x, a1.y, a1.z, a1.w};
            float wn[8] = {w0.x, w0.y, w0.z, w0.w, w1.x, w1.y, w1.z, w1.w};
#pragma unroll
            for (int i = 0; i < 8; ++i)
#pragma unroll
                for (int j = 0; j < 8; ++j) acc[i][j] = fmaf(am[i], wn[j], acc[i][j]);
        }
        __syncthreads();
    }

    float4 bias0 = *(const float4*)&b_ih[n0 + tn];
    float4 bias1 = *(const float4*)&b_ih[n0 + tn + 64];
    float bs[8] = {bias0.x, bias0.y, bias0.z, bias0.w, bias1.x, bias1.y, bias1.z, bias1.w};
#pragma unroll
    for (int i = 0; i < 8; ++i) {
        int m = (i < 4) ? (tm + i) : (tm + 60 + i);
        float* orow = g_gi + ((size_t)b * Sdim + t0 + m) * G3 + n0;
        *(float4*)(orow + tn)      = make_float4(acc[i][0] + bs[0], acc[i][1] + bs[1],
                                                 acc[i][2] + bs[2], acc[i][3] + bs[3]);
        *(float4*)(orow + tn + 64) = make_float4(acc[i][4] + bs[4], acc[i][5] + bs[5],
                                                 acc[i][6] + bs[6], acc[i][7] + bs[7]);
    }
}

// ---------------------------------------------------------------------------
// Kernel 2: persistent GRU recurrence v6: 512 threads (4 warps/SMSP).
// Thread (jg: jt pair, bh: batch half, kc: k-pair class mod 8): 3 gates x
// 2 jt x 4 batch rows, k pairs {kc+8m}. W LDS.64: 16 distinct 8B slots fill
// 128B (WS=264 -> jgl offset 64B), bh lanes broadcast-dedup -> 1 phase.
// h LDS.64: bh offset 64B (HS=260) -> 1 phase. Crossbar 2560 cyc/step.
// 3-round reduce-scatter over (kc) -> lane owns (b=4bh+(kc&3), jl=kc>>2):
// 512 threads = full 8x64 output slice, fully parallel epilogue.
// ---------------------------------------------------------------------------
#define WS 264
#define HS 260
#define WS_FLOATS (192 * WS)      // 50688
#define HB_FLOATS (2 * 8 * HS)    // 4160
#define RSM_BYTES ((WS_FLOATS + HB_FLOATS + 8) * 4)   // 219,424 B

__device__ __forceinline__ float sigm(float x) {
    return __fdividef(1.f, 1.f + __expf(-x));
}
__device__ __forceinline__ float tanh_e(float x) {
    return __fdividef(2.f, 1.f + __expf(-2.f * x)) - 1.f;
}

__global__ __launch_bounds__(512, 1) __cluster_dims__(4, 1, 1)
void gru_rec_kernel(const float* __restrict__ tree,
                    const int*   __restrict__ mask,
                    const float* __restrict__ W_hh,
                    const float* __restrict__ b_hh,
                    float*       __restrict__ out) {
    extern __shared__ __align__(16) float sm[];
    float* W_s   = sm;                    // [192][264]: row = gate*64 + jt_local
    float* h_buf = sm + WS_FLOATS;        // [2][8][260]: [p][b][k 0..255]
    int*   li_s  = (int*)(h_buf + HB_FLOATS);

    const int tid = threadIdx.x;
    const int r   = blockIdx.x & 3;
    const int b0  = (blockIdx.x >> 2) * 8;

    for (int i = tid; i < 192 * 256; i += 512) {
        int row = i >> 8, k = i & 255;
        int grow = (row >> 6) * 256 + r * 64 + (row & 63);
        W_s[row * WS + k] = W_hh[(size_t)grow * 256 + k];
    }
    for (int i = tid; i < 8 * 256; i += 512)
        h_buf[(i >> 8) * HS + (i & 255)] = tree[(size_t)b0 * 256 + i];
    {
        int w = tid >> 5, ln = tid & 31;
        if (w < 8) {
            int s = 0;
            for (int i = ln; i < 512; i += 32) s += mask[(size_t)(b0 + w) * 512 + i];
#pragma unroll
            for (int o = 16; o; o >>= 1) s += __shfl_xor_sync(0xffffffffu, s, o);
            if (ln == 0) li_s[w] = (s > 0) ? (s - 1) : 0;
        }
    }
    __syncthreads();
    asm volatile("barrier.cluster.arrive.aligned;" ::: "memory");
    asm volatile("barrier.cluster.wait.aligned;" ::: "memory");

    const int lane = tid & 31;
    const int w    = tid >> 5;
    const int jgl  = lane >> 4;          // which of the warp's 2 jt pairs
    const int bh   = (lane >> 3) & 1;    // batch half
    const int kc   = lane & 7;           // k-pair class (mod 8)
    const int jg   = w * 2 + jgl;        // jt pair: dims {2jg, 2jg+1}

    // final ownership after reduce-scatter
    const int jl_own = kc >> 2;
    const int b_own  = bh * 4 + (kc & 3);
    const int dim    = 2 * jg + jl_own;
    const int kglob  = r * 64 + dim;

    const float* wb[3][2];
#pragma unroll
    for (int g = 0; g < 3; ++g)
#pragma unroll
        for (int jl = 0; jl < 2; ++jl)
            wb[g][jl] = W_s + (g * 64 + 2 * jg + jl) * WS + kc * 2;

    const float bhr = b_hh[kglob];
    const float bhz = b_hh[256 + kglob];
    const float bhn = b_hh[512 + kglob];
    const int li = li_s[b_own];

    uint32_t hb_u32;
    asm("{ .reg .u64 t0; cvta.to.shared.u64 t0, %1; cvt.u32.u64 %0, t0; }"
        : "=r"(hb_u32) : "l"(h_buf));
    uint32_t peer[4];
#pragma unroll
    for (int q = 0; q < 4; ++q)
        asm("mapa.shared::cluster.u32 %0, %1, %2;" : "=r"(peer[q]) : "r"(hb_u32), "r"(q));

    const float* gp = g_gi + ((size_t)(b0 + b_own) * Sdim) * G3 + kglob;
    float gr = __ldg(gp), gz = __ldg(gp + 256), gn = __ldg(gp + 512);

    const int k0 = kc & 1, k1 = (kc >> 1) & 1, k2 = (kc >> 2) & 1;

    int p = 0;
    for (int t = 0; t < Sdim; ++t) {
        const float* hbp = h_buf + p * (8 * HS) + bh * (4 * HS) + kc * 2;
        u64 acc[3][2][4];
#pragma unroll
        for (int g = 0; g < 3; ++g)
#pragma unroll
            for (int jl = 0; jl < 2; ++jl)
#pragma unroll
                for (int b = 0; b < 4; ++b) acc[g][jl][b] = 0ull;

#pragma unroll 4
        for (int m = 0; m < 16; ++m) {
            u64 wv[3][2];
#pragma unroll
            for (int g = 0; g < 3; ++g)
#pragma unroll
                for (int jl = 0; jl < 2; ++jl)
                    wv[g][jl] = *(const u64*)(wb[g][jl] + 16 * m);
#pragma unroll
            for (int b = 0; b < 4; ++b) {
                u64 hv = *(const u64*)(hbp + b * HS + 16 * m);
#pragma unroll
                for (int g = 0; g < 3; ++g)
#pragma unroll
                    for (int jl = 0; jl < 2; ++jl)
                        acc[g][jl][b] = ffma2(wv[g][jl], hv, acc[g][jl][b]);
            }
        }

        // ---- reduce-scatter over kc (3 xor rounds) -------------------------
        float s0[3][2][4];
#pragma unroll
        for (int g = 0; g < 3; ++g)
#pragma unroll
            for (int jl = 0; jl < 2; ++jl)
#pragma unroll
                for (int b = 0; b < 4; ++b) {
                    float lo, hi; unpack2(acc[g][jl][b], lo, hi);
                    s0[g][jl][b] = lo + hi;
                }
        float s1[3][2][2];
#pragma unroll
        for (int g = 0; g < 3; ++g)
#pragma unroll
            for (int jl = 0; jl < 2; ++jl)
#pragma unroll
                for (int b = 0; b < 2; ++b) {
                    float e = s0[g][jl][2 * b], o = s0[g][jl][2 * b + 1];
                    float keep = k0 ? o : e, send = k0 ? e : o;
                    s1[g][jl][b] = keep + __shfl_xor_sync(0xffffffffu, send, 1);
                }
        float s2[3][2];
#pragma unroll
        for (int g = 0; g < 3; ++g)
#pragma unroll
            for (int jl = 0; jl < 2; ++jl) {
                float e = s1[g][jl][0], o = s1[g][jl][1];
                float keep = k1 ? o : e, send = k1 ? e : o;
                s2[g][jl] = keep + __shfl_xor_sync(0xffffffffu, send, 2);
            }
        float sf[3];
#pragma unroll
        for (int g = 0; g < 3; ++g) {
            float e = s2[g][0], o = s2[g][1];
            float keep = k2 ? o : e, send = k2 ? e : o;
            sf[g] = keep + __shfl_xor_sync(0xffffffffu, send, 4);
        }

        // ---- epilogue: this thread owns (b_own, kglob) ---------------------
        float hold = h_buf[p * (8 * HS) + b_own * HS + kglob];
        float rg = sigm(gr + bhr + sf[0]);
        float zg = sigm(gz + bhz + sf[1]);
        float ng = tanh_e(fmaf(rg, sf[2] + bhn, gn));
        float hn = fmaf(zg, hold - ng, ng);

        if (t == li) out[(size_t)(b0 + b_own) * 256 + kglob] = hn;

        int pn = p ^ 1;
        uint32_t off = (uint32_t)(((pn * 8 + b_own) * HS + kglob) * 4);
#pragma unroll
        for (int q = 0; q < 4; ++q)
            asm volatile("st.shared::cluster.f32 [%0], %1;"
                         :: "r"(peer[q] + off), "f"(hn) : "memory");

        asm volatile("barrier.cluster.arrive.aligned;" ::: "memory");
        gp += G3;
        if (t + 1 < Sdim) {           // gi(t+1) prefetch hidden under barrier wait
            gr = __ldg(gp); gz = __ldg(gp + 256); gn = __ldg(gp + 512);
        }
        asm volatile("barrier.cluster.wait.aligned;" ::: "memory");
        p = pn;
    }
}

// ---------------------------------------------------------------------------
extern "C" void kernel_launch(void* const* d_in, const int* in_sizes, int n_in,
                              void* d_out, int out_size) {
    const float* tree  = (const float*)d_in[0];
    const float* seq   = (const float*)d_in[1];
    const int*   mask  = (const int*)  d_in[2];
    const float* W_ih  = (const float*)d_in[3];
    const float* W_hh  = (const float*)d_in[4];
    const float* b_ih  = (const float*)d_in[5];
    const float* b_hh  = (const float*)d_in[6];
    float* out = (float*)d_out;

    dim3 g1((Bdim * Sdim) / 128, G3 / 128);
    gi_gemm_kernel<<<g1, 256>>>(seq, W_ih, b_ih);

    cudaFuncSetAttribute(gru_rec_kernel,
                         cudaFuncAttributeMaxDynamicSharedMemorySize, RSM_BYTES);
    gru_rec_kernel<<<128, 512, RSM_BYTES>>>(tree, mask, W_hh, b_hh, out);
}

// round 7
// speedup vs baseline: 1.1499x; 1.1499x over previous
#include <cuda_runtime.h>
#include <cstdint>

#define Hdim 256
#define Sdim 512
#define Bdim 256
#define G3   768

// 402 MB scratch for precomputed input-gate activations gi[b*S + t][768]
__device__ float g_gi[(size_t)Bdim * Sdim * G3];

// ---- f32x2 helpers ---------------------------------------------------------
typedef unsigned long long u64;
__device__ __forceinline__ u64 pack2(float lo, float hi) {
    u64 r; asm("mov.b64 %0,{%1,%2};" : "=l"(r) : "f"(lo), "f"(hi)); return r;
}
__device__ __forceinline__ void unpack2(u64 v, float& lo, float& hi) {
    asm("mov.b64 {%0,%1},%2;" : "=f"(lo), "=f"(hi) : "l"(v));
}
__device__ __forceinline__ u64 ffma2(u64 a, u64 b, u64 c) {
    u64 d; asm("fma.rn.f32x2 %0,%1,%2,%3;" : "=l"(d) : "l"(a), "l"(b), "l"(c));
    return d;
}

// ---------------------------------------------------------------------------
// Kernel 1: gi = x @ W_ih^T + b_ih (v1 — at SIMT fp32 roofline, ~1.44 ms).
// ---------------------------------------------------------------------------
__global__ __launch_bounds__(256) void gi_gemm_kernel(const float* __restrict__ seq,
                                                      const float* __restrict__ W_ih,
                                                      const float* __restrict__ b_ih) {
    __shared__ float As[32 * 128];
    __shared__ float Ws[32 * 132];
    const int tid = threadIdx.x;
    const int b   = blockIdx.x >> 2;
    const int t0  = (blockIdx.x & 3) * 128;
    const int n0  = blockIdx.y * 128;
    const float* seqb = seq + (size_t)b * (Hdim * Sdim);

    const int tm = (tid & 15) * 4;
    const int tn = (tid >> 4) * 4;
    const int lane = tid & 31, wp = tid >> 5;

    float acc[8][8];
#pragma unroll
    for (int i = 0; i < 8; ++i)
#pragma unroll
        for (int j = 0; j < 8; ++j) acc[i][j] = 0.f;

    for (int kt = 0; kt < 8; ++kt) {
        int pos = tid;
#pragma unroll
        for (int i = 0; i < 4; ++i, pos += 256) {
            int k  = pos >> 5;
            int mq = (pos & 31) << 2;
            float4 v = *(const float4*)(seqb + (size_t)(kt * 32 + k) * Sdim + t0 + mq);
            *(float4*)&As[k * 128 + mq] = v;
        }
#pragma unroll
        for (int i = 0; i < 16; ++i) {
            int n = wp * 16 + i;
            Ws[lane * 132 + n] = W_ih[(size_t)(n0 + n) * Hdim + kt * 32 + lane];
        }
        __syncthreads();
#pragma unroll
        for (int kk = 0; kk < 32; ++kk) {
            float4 a0 = *(const float4*)&As[kk * 128 + tm];
            float4 a1 = *(const float4*)&As[kk * 128 + tm + 64];
            float4 w0 = *(const float4*)&Ws[kk * 132 + tn];
            float4 w1 = *(const float4*)&Ws[kk * 132 + tn + 64];
            float am[8] = {a0.x, a0.y, a0.z, a0.w, a1.x, a1.y, a1.z, a1.w};
            float wn[8] = {w0.x, w0.y, w0.z, w0.w, w1.x, w1.y, w1.z, w1.w};
#pragma unroll
            for (int i = 0; i < 8; ++i)
#pragma unroll
                for (int j = 0; j < 8; ++j) acc[i][j] = fmaf(am[i], wn[j], acc[i][j]);
        }
        __syncthreads();
    }

    float4 bias0 = *(const float4*)&b_ih[n0 + tn];
    float4 bias1 = *(const float4*)&b_ih[n0 + tn + 64];
    float bs[8] = {bias0.x, bias0.y, bias0.z, bias0.w, bias1.x, bias1.y, bias1.z, bias1.w};
#pragma unroll
    for (int i = 0; i < 8; ++i) {
        int m = (i < 4) ? (tm + i) : (tm + 60 + i);
        float* orow = g_gi + ((size_t)b * Sdim + t0 + m) * G3 + n0;
        *(float4*)(orow + tn)      = make_float4(acc[i][0] + bs[0], acc[i][1] + bs[1],
                                                 acc[i][2] + bs[2], acc[i][3] + bs[3]);
        *(float4*)(orow + tn + 64) = make_float4(acc[i][4] + bs[4], acc[i][5] + bs[5],
                                                 acc[i][6] + bs[6], acc[i][7] + bs[7]);
    }
}

// ---------------------------------------------------------------------------
// Kernel 2: persistent GRU recurrence v7 = v5 shape + LDS.128 k-quads.
// 256 threads; thread (jg = w*4 + lane>>3: jt pair, kc = lane&7: k-quad class).
// Per m (8 iters): 6 W LDS.128 + 8 h LDS.128 -> 96 FFMA2 (ratio 96:14).
// W LDS.128: 32 distinct 16B = 512B = 4 phases (floor-optimal).
// h LDS.128: kc spans exactly 128B, 4x jg dedup -> 1 phase.
// Crossbar 2048 cyc/step. Reduce-scatter/epilogue/DSMEM identical to v5.
// ---------------------------------------------------------------------------
#define WS 264
#define HS 260
#define WS_FLOATS (192 * WS)      // 50688
#define HB_FLOATS (2 * 8 * HS)    // 4160
#define RSM_BYTES ((WS_FLOATS + HB_FLOATS + 8) * 4)

__device__ __forceinline__ float sigm(float x) {
    return __fdividef(1.f, 1.f + __expf(-x));
}
__device__ __forceinline__ float tanh_e(float x) {
    return __fdividef(2.f, 1.f + __expf(-2.f * x)) - 1.f;
}

__global__ __launch_bounds__(256, 1) __cluster_dims__(4, 1, 1)
void gru_rec_kernel(const float* __restrict__ tree,
                    const int*   __restrict__ mask,
                    const float* __restrict__ W_hh,
                    const float* __restrict__ b_hh,
                    float*       __restrict__ out) {
    extern __shared__ __align__(16) float sm[];
    float* W_s   = sm;                    // [192][264]: row = gate*64 + jt_local
    float* h_buf = sm + WS_FLOATS;        // [2][8][260]: [p][b][k]
    int*   li_s  = (int*)(h_buf + HB_FLOATS);

    const int tid = threadIdx.x;
    const int r   = blockIdx.x & 3;
    const int b0  = (blockIdx.x >> 2) * 8;

    for (int i = tid; i < 192 * 256; i += 256) {
        int row = i >> 8, k = i & 255;
        int grow = (row >> 6) * 256 + r * 64 + (row & 63);
        W_s[row * WS + k] = W_hh[(size_t)grow * 256 + k];
    }
    for (int i = tid; i < 8 * 256; i += 256)
        h_buf[(i >> 8) * HS + (i & 255)] = tree[(size_t)b0 * 256 + i];
    {
        int bb = tid >> 5, ln = tid & 31;
        int s = 0;
        for (int i = ln; i < 512; i += 32) s += mask[(size_t)(b0 + bb) * 512 + i];
#pragma unroll
        for (int o = 16; o; o >>= 1) s += __shfl_xor_sync(0xffffffffu, s, o);
        if (ln == 0) li_s[bb] = (s > 0) ? (s - 1) : 0;
    }
    __syncthreads();
    asm volatile("barrier.cluster.arrive.aligned;" ::: "memory");
    asm volatile("barrier.cluster.wait.aligned;" ::: "memory");

    const int lane = tid & 31;
    const int w    = tid >> 5;
    const int kc   = lane & 7;            // k-quad class AND final owned batch row
    const int jg   = w * 4 + (lane >> 3); // 0..31 -> jt pair {2jg, 2jg+1}
    const int kglob = r * 64 + jg * 2;

    const float* wb[3][2];
#pragma unroll
    for (int g = 0; g < 3; ++g)
#pragma unroll
        for (int jl = 0; jl < 2; ++jl)
            wb[g][jl] = W_s + (g * 64 + jg * 2 + jl) * WS + kc * 4;

    const float2 bhr2 = *(const float2*)(b_hh + kglob);
    const float2 bhz2 = *(const float2*)(b_hh + 256 + kglob);
    const float2 bhn2 = *(const float2*)(b_hh + 512 + kglob);
    const int li = li_s[kc];

    uint32_t hb_u32;
    asm("{ .reg .u64 t0; cvta.to.shared.u64 t0, %1; cvt.u32.u64 %0, t0; }"
        : "=r"(hb_u32) : "l"(h_buf));
    uint32_t peer[4];
#pragma unroll
    for (int q = 0; q < 4; ++q)
        asm("mapa.shared::cluster.u32 %0, %1, %2;" : "=r"(peer[q]) : "r"(hb_u32), "r"(q));

    const float* gp = g_gi + ((size_t)(b0 + kc) * Sdim) * G3 + kglob;
    float2 gr2 = *(const float2*)(gp);
    float2 gz2 = *(const float2*)(gp + 256);
    float2 gn2 = *(const float2*)(gp + 512);

    const int k0 = kc & 1, k1 = (kc >> 1) & 1, k2 = (kc >> 2) & 1;

    int p = 0;
    for (int t = 0; t < Sdim; ++t) {
        const float* hbp = h_buf + p * (8 * HS) + kc * 4;
        u64 acc[3][2][8];
#pragma unroll
        for (int g = 0; g < 3; ++g)
#pragma unroll
            for (int jl = 0; jl < 2; ++jl)
#pragma unroll
                for (int b = 0; b < 8; ++b) acc[g][jl][b] = 0ull;

#pragma unroll
        for (int m = 0; m < 8; ++m) {
            ulonglong2 wv[3][2];
#pragma unroll
            for (int g = 0; g < 3; ++g)
#pragma unroll
                for (int jl = 0; jl < 2; ++jl)
                    wv[g][jl] = *(const ulonglong2*)(wb[g][jl] + 32 * m);
#pragma unroll
            for (int b = 0; b < 8; ++b) {
                ulonglong2 hv = *(const ulonglong2*)(hbp + b * HS + 32 * m);
#pragma unroll
                for (int g = 0; g < 3; ++g)
#pragma unroll
                    for (int jl = 0; jl < 2; ++jl) {
                        acc[g][jl][b] = ffma2(wv[g][jl].x, hv.x, acc[g][jl][b]);
                        acc[g][jl][b] = ffma2(wv[g][jl].y, hv.y, acc[g][jl][b]);
                    }
            }
        }

        // ---- reduce-scatter over kc (3 xor rounds), final b = kc ----------
        float s0[3][2][8];
#pragma unroll
        for (int g = 0; g < 3; ++g)
#pragma unroll
            for (int jl = 0; jl < 2; ++jl)
#pragma unroll
                for (int b = 0; b < 8; ++b) {
                    float lo, hi; unpack2(acc[g][jl][b], lo, hi);
                    s0[g][jl][b] = lo + hi;
                }
        float s1[3][2][4];
#pragma unroll
        for (int g = 0; g < 3; ++g)
#pragma unroll
            for (int jl = 0; jl < 2; ++jl)
#pragma unroll
                for (int b = 0; b < 4; ++b) {
                    float e = s0[g][jl][2 * b], o = s0[g][jl][2 * b + 1];
                    float keep = k0 ? o : e, send = k0 ? e : o;
                    s1[g][jl][b] = keep + __shfl_xor_sync(0xffffffffu, send, 1);
                }
        float s2[3][2][2];
#pragma unroll
        for (int g = 0; g < 3; ++g)
#pragma unroll
            for (int jl = 0; jl < 2; ++jl)
#pragma unroll
                for (int b = 0; b < 2; ++b) {
                    float e = s1[g][jl][2 * b], o = s1[g][jl][2 * b + 1];
                    float keep = k1 ? o : e, send = k1 ? e : o;
                    s2[g][jl][b] = keep + __shfl_xor_sync(0xffffffffu, send, 2);
                }
        float sf[3][2];
#pragma unroll
        for (int g = 0; g < 3; ++g)
#pragma unroll
            for (int jl = 0; jl < 2; ++jl) {
                float e = s2[g][jl][0], o = s2[g][jl][1];
                float keep = k2 ? o : e, send = k2 ? e : o;
                sf[g][jl] = keep + __shfl_xor_sync(0xffffffffu, send, 4);
            }

        // ---- epilogue: batch row kc, dims kglob, kglob+1 -------------------
        const float2 hold2 = *(const float2*)(h_buf + p * (8 * HS) + kc * HS + kglob);
        float r0 = sigm(gr2.x + bhr2.x + sf[0][0]);
        float z0 = sigm(gz2.x + bhz2.x + sf[1][0]);
        float n0 = tanh_e(fmaf(r0, sf[2][0] + bhn2.x, gn2.x));
        float hn0 = fmaf(z0, hold2.x - n0, n0);
        float r1 = sigm(gr2.y + bhr2.y + sf[0][1]);
        float z1 = sigm(gz2.y + bhz2.y + sf[1][1]);
        float n1 = tanh_e(fmaf(r1, sf[2][1] + bhn2.y, gn2.y));
        float hn1 = fmaf(z1, hold2.y - n1, n1);

        if (t == li)
            *(float2*)(out + (size_t)(b0 + kc) * 256 + kglob) = make_float2(hn0, hn1);

        int pn = p ^ 1;
        u64 hv2 = pack2(hn0, hn1);
        uint32_t off = (uint32_t)(((pn * 8 + kc) * HS + kglob) * 4);
#pragma unroll
        for (int q = 0; q < 4; ++q)
            asm volatile("st.shared::cluster.u64 [%0], %1;"
                         :: "r"(peer[q] + off), "l"(hv2) : "memory");

        asm volatile("barrier.cluster.arrive.aligned;" ::: "memory");
        gp += G3;
        if (t + 1 < Sdim) {           // gi(t+1) prefetch hidden under barrier wait
            gr2 = *(const float2*)(gp);
            gz2 = *(const float2*)(gp + 256);
            gn2 = *(const float2*)(gp + 512);
        }
        asm volatile("barrier.cluster.wait.aligned;" ::: "memory");
        p = pn;
    }
}

// ---------------------------------------------------------------------------
extern "C" void kernel_launch(void* const* d_in, const int* in_sizes, int n_in,
                              void* d_out, int out_size) {
    const float* tree  = (const float*)d_in[0];
    const float* seq   = (const float*)d_in[1];
    const int*   mask  = (const int*)  d_in[2];
    const float* W_ih  = (const float*)d_in[3];
    const float* W_hh  = (const float*)d_in[4];
    const float* b_ih  = (const float*)d_in[5];
    const float* b_hh  = (const float*)d_in[6];
    float* out = (float*)d_out;

    dim3 g1((Bdim * Sdim) / 128, G3 / 128);
    gi_gemm_kernel<<<g1, 256>>>(seq, W_ih, b_ih);

    cudaFuncSetAttribute(gru_rec_kernel,
                         cudaFuncAttributeMaxDynamicSharedMemorySize, RSM_BYTES);
    gru_rec_kernel<<<128, 256, RSM_BYTES>>>(tree, mask, W_hh, b_hh, out);
}

// round 9
// speedup vs baseline: 1.4664x; 1.2752x over previous
#include <cuda_runtime.h>
#include <cuda_bf16.h>
#include <mma.h>
#include <cstdint>

using namespace nvcuda;

#define Hdim 256
#define Sdim 512
#define Bdim 256
#define G3   768

// Scratch: gi activations + bf16 hi/lo splits of A (transposed) and W
__device__ float g_gi[(size_t)Bdim * Sdim * G3];                 // 402 MB
__device__ __nv_bfloat16 g_Ah[(size_t)Bdim * Sdim * Hdim];       // 67 MB, [m][k]
__device__ __nv_bfloat16 g_Al[(size_t)Bdim * Sdim * Hdim];
__device__ __nv_bfloat16 g_Wh[(size_t)G3 * Hdim];                // [n][k]
__device__ __nv_bfloat16 g_Wl[(size_t)G3 * Hdim];

typedef unsigned long long u64;
__device__ __forceinline__ u64 pack2(float lo, float hi) {
    u64 r; asm("mov.b64 %0,{%1,%2};" : "=l"(r) : "f"(lo), "f"(hi)); return r;
}
__device__ __forceinline__ void unpack2(u64 v, float& lo, float& hi) {
    asm("mov.b64 {%0,%1},%2;" : "=f"(lo), "=f"(hi) : "l"(v));
}
__device__ __forceinline__ u64 ffma2(u64 a, u64 b, u64 c) {
    u64 d; asm("fma.rn.f32x2 %0,%1,%2,%3;" : "=l"(d) : "l"(a), "l"(b), "l"(c));
    return d;
}

// ---------------------------------------------------------------------------
// Convert kernels: bf16 hi/lo split (x = hi + lo, both bf16)
// ---------------------------------------------------------------------------
__global__ void convert_w_kernel(const float* __restrict__ W_ih) {
    int n = blockIdx.x, k = threadIdx.x;
    float v = W_ih[(size_t)n * Hdim + k];
    __nv_bfloat16 hi = __float2bfloat16(v);
    __nv_bfloat16 lo = __float2bfloat16(v - __bfloat162float(hi));
    g_Wh[(size_t)n * Hdim + k] = hi;
    g_Wl[(size_t)n * Hdim + k] = lo;
}

// Transpose seq (B,H,S) -> A[m=b*512+t][k], split to bf16 hi/lo.
__global__ __launch_bounds__(256) void convert_seq_kernel(const float* __restrict__ seq) {
    __shared__ float sm[32 * 65];
    int b  = blockIdx.x;
    int k0 = blockIdx.y * 32;
    int t0 = blockIdx.z * 64;
    int tid = threadIdx.x;
    const float* sb = seq + (size_t)b * (Hdim * Sdim);
#pragma unroll
    for (int p = 0; p < 8; ++p) {
        int i = p * 256 + tid;
        int k = i >> 6, t = i & 63;
        sm[k * 65 + t] = sb[(size_t)(k0 + k) * Sdim + t0 + t];
    }
    __syncthreads();
#pragma unroll
    for (int p = 0; p < 8; ++p) {
        int i = p * 256 + tid;
        int tl = i >> 5, kk = i & 31;
        float v = sm[kk * 65 + tl];
        __nv_bfloat16 hi = __float2bfloat16(v);
        __nv_bfloat16 lo = __float2bfloat16(v - __bfloat162float(hi));
        size_t o = ((size_t)b * Sdim + t0 + tl) * Hdim + k0 + kk;
        g_Ah[o] = hi;
        g_Al[o] = lo;
    }
}

// ---------------------------------------------------------------------------
// Kernel 1: gi = x @ W_ih^T + b_ih via bf16 WMMA (HMMA), 3-product split:
//   gi ~= Ah*Wh + Al*Wh + Ah*Wl    (fp32 accum; error ~eps^2)
// CTA 128x128, 8 warps (4m x 2n), warp tile 32x64 = 2x4 wmma 16x16x16.
// Bias folded in by initializing accumulators from a broadcast bias tile.
// smem tiles ldm=40 bf16 (80B rows: 16B-aligned, 8-row groups conflict-free).
// ---------------------------------------------------------------------------
#define LDT 40
#define GA_H 0
#define GA_L 10240
#define GB_H 20480
#define GB_L 30720
#define G_BIAS 40960
#define GSM_TOTAL (G_BIAS + 16 * 128 * 4)   // 49,152 B

__global__ __launch_bounds__(256) void gi_mma_kernel(const float* __restrict__ b_ih) {
    extern __shared__ __align__(16) char smg[];
    __nv_bfloat16* As_h = (__nv_bfloat16*)(smg + GA_H);
    __nv_bfloat16* As_l = (__nv_bfloat16*)(smg + GA_L);
    __nv_bfloat16* Bs_h = (__nv_bfloat16*)(smg + GB_H);
    __nv_bfloat16* Bs_l = (__nv_bfloat16*)(smg + GB_L);
    float*         bias = (float*)(smg + G_BIAS);

    const int tid = threadIdx.x;
    const int wid = tid >> 5;
    const int wm  = wid >> 1;        // 0..3 -> warp rows [wm*32, +32)
    const int wn  = wid & 1;         // 0..1 -> warp cols [wn*64, +64)
    const size_t mbase = (size_t)blockIdx.x * 128;
    const int    n0    = blockIdx.y * 128;

    // bias broadcast tile: 16 identical rows of 128
    for (int i = tid; i < 16 * 128; i += 256) bias[i] = b_ih[n0 + (i & 127)];
    __syncthreads();

    wmma::fragment<wmma::accumulator, 16, 16, 16, float> c[2][4];
#pragma unroll
    for (int i = 0; i < 2; ++i)
#pragma unroll
        for (int j = 0; j < 4; ++j)
            wmma::load_matrix_sync(c[i][j], bias + wn * 64 + j * 16, 128,
                                   wmma::mem_row_major);

    for (int kb = 0; kb < 8; ++kb) {
        // load A/B hi+lo tiles: 128 rows x 32 k (uint4 = 8 bf16)
#pragma unroll
        for (int q = 0; q < 2; ++q) {
            int i = tid + q * 256;
            int row = i >> 2, g = i & 3;
            size_t ga = (mbase + row) * Hdim + kb * 32 + g * 8;
            size_t gb = (size_t)(n0 + row) * Hdim + kb * 32 + g * 8;
            int so = row * LDT + g * 8;
            *(uint4*)(As_h + so) = *(const uint4*)(g_Ah + ga);
            *(uint4*)(As_l + so) = *(const uint4*)(g_Al + ga);
            *(uint4*)(Bs_h + so) = *(const uint4*)(g_Wh + gb);
            *(uint4*)(Bs_l + so) = *(const uint4*)(g_Wl + gb);
        }
        __syncthreads();

#pragma unroll
        for (int ks = 0; ks < 2; ++ks) {
            wmma::fragment<wmma::matrix_a, 16, 16, 16, __nv_bfloat16, wmma::row_major> ah[2], al[2];
            wmma::fragment<wmma::matrix_b, 16, 16, 16, __nv_bfloat16, wmma::col_major> bh[4], bl[4];
#pragma unroll
            for (int i = 0; i < 2; ++i) {
                const __nv_bfloat16* pa = As_h + (wm * 32 + i * 16) * LDT + ks * 16;
                const __nv_bfloat16* qa = As_l + (wm * 32 + i * 16) * LDT + ks * 16;
                wmma::load_matrix_sync(ah[i], pa, LDT);
                wmma::load_matrix_sync(al[i], qa, LDT);
            }
#pragma unroll
            for (int j = 0; j < 4; ++j) {
                const __nv_bfloat16* pb = Bs_h + (wn * 64 + j * 16) * LDT + ks * 16;
                const __nv_bfloat16* qb = Bs_l + (wn * 64 + j * 16) * LDT + ks * 16;
                wmma::load_matrix_sync(bh[j], pb, LDT);
                wmma::load_matrix_sync(bl[j], qb, LDT);
            }
#pragma unroll
            for (int i = 0; i < 2; ++i)
#pragma unroll
                for (int j = 0; j < 4; ++j) {
                    wmma::mma_sync(c[i][j], ah[i], bh[j], c[i][j]);
                    wmma::mma_sync(c[i][j], al[i], bh[j], c[i][j]);
                    wmma::mma_sync(c[i][j], ah[i], bl[j], c[i][j]);
                }
        }
        __syncthreads();
    }

    // store to g_gi (row-major, ldm = G3)
#pragma unroll
    for (int i = 0; i < 2; ++i)
#pragma unroll
        for (int j = 0; j < 4; ++j) {
            float* dst = g_gi + (mbase + wm * 32 + i * 16) * G3 + n0 + wn * 64 + j * 16;
            wmma::store_matrix_sync(dst, c[i][j], G3, wmma::mem_row_major);
        }
}

// ---------------------------------------------------------------------------
// Kernel 2: persistent GRU recurrence v7 (unchanged — 1.62 ms measured).
// ---------------------------------------------------------------------------
#define WS 264
#define HS 260
#define WS_FLOATS (192 * WS)
#define HB_FLOATS (2 * 8 * HS)
#define RSM_BYTES ((WS_FLOATS + HB_FLOATS + 8) * 4)

__device__ __forceinline__ float sigm(float x) {
    return __fdividef(1.f, 1.f + __expf(-x));
}
__device__ __forceinline__ float tanh_e(float x) {
    return __fdividef(2.f, 1.f + __expf(-2.f * x)) - 1.f;
}

__global__ __launch_bounds__(256, 1) __cluster_dims__(4, 1, 1)
void gru_rec_kernel(const float* __restrict__ tree,
                    const int*   __restrict__ mask,
                    const float* __restrict__ W_hh,
                    const float* __restrict__ b_hh,
                    float*       __restrict__ out) {
    extern __shared__ __align__(16) float sm[];
    float* W_s   = sm;
    float* h_buf = sm + WS_FLOATS;
    int*   li_s  = (int*)(h_buf + HB_FLOATS);

    const int tid = threadIdx.x;
    const int r   = blockIdx.x & 3;
    const int b0  = (blockIdx.x >> 2) * 8;

    for (int i = tid; i < 192 * 256; i += 256) {
        int row = i >> 8, k = i & 255;
        int grow = (row >> 6) * 256 + r * 64 + (row & 63);
        W_s[row * WS + k] = W_hh[(size_t)grow * 256 + k];
    }
    for (int i = tid; i < 8 * 256; i += 256)
        h_buf[(i >> 8) * HS + (i & 255)] = tree[(size_t)b0 * 256 + i];
    {
        int bb = tid >> 5, ln = tid & 31;
        int s = 0;
        for (int i = ln; i < 512; i += 32) s += mask[(size_t)(b0 + bb) * 512 + i];
#pragma unroll
        for (int o = 16; o; o >>= 1) s += __shfl_xor_sync(0xffffffffu, s, o);
        if (ln == 0) li_s[bb] = (s > 0) ? (s - 1) : 0;
    }
    __syncthreads();
    asm volatile("barrier.cluster.arrive.aligned;" ::: "memory");
    asm volatile("barrier.cluster.wait.aligned;" ::: "memory");

    const int lane = tid & 31;
    const int w    = tid >> 5;
    const int kc   = lane & 7;
    const int jg   = w * 4 + (lane >> 3);
    const int kglob = r * 64 + jg * 2;

    const float* wb[3][2];
#pragma unroll
    for (int g = 0; g < 3; ++g)
#pragma unroll
        for (int jl = 0; jl < 2; ++jl)
            wb[g][jl] = W_s + (g * 64 + jg * 2 + jl) * WS + kc * 4;

    const float2 bhr2 = *(const float2*)(b_hh + kglob);
    const float2 bhz2 = *(const float2*)(b_hh + 256 + kglob);
    const float2 bhn2 = *(const float2*)(b_hh + 512 + kglob);
    const int li = li_s[kc];

    uint32_t hb_u32;
    asm("{ .reg .u64 t0; cvta.to.shared.u64 t0, %1; cvt.u32.u64 %0, t0; }"
        : "=r"(hb_u32) : "l"(h_buf));
    uint32_t peer[4];
#pragma unroll
    for (int q = 0; q < 4; ++q)
        asm("mapa.shared::cluster.u32 %0, %1, %2;" : "=r"(peer[q]) : "r"(hb_u32), "r"(q));

    const float* gp = g_gi + ((size_t)(b0 + kc) * Sdim) * G3 + kglob;
    float2 gr2 = *(const float2*)(gp);
    float2 gz2 = *(const float2*)(gp + 256);
    float2 gn2 = *(const float2*)(gp + 512);

    const int k0 = kc & 1, k1 = (kc >> 1) & 1, k2 = (kc >> 2) & 1;

    int p = 0;
    for (int t = 0; t < Sdim; ++t) {
        const float* hbp = h_buf + p * (8 * HS) + kc * 4;
        u64 acc[3][2][8];
#pragma unroll
        for (int g = 0; g < 3; ++g)
#pragma unroll
            for (int jl = 0; jl < 2; ++jl)
#pragma unroll
                for (int b = 0; b < 8; ++b) acc[g][jl][b] = 0ull;

#pragma unroll
        for (int m = 0; m < 8; ++m) {
            ulonglong2 wv[3][2];
#pragma unroll
            for (int g = 0; g < 3; ++g)
#pragma unroll
                for (int jl = 0; jl < 2; ++jl)
                    wv[g][jl] = *(const ulonglong2*)(wb[g][jl] + 32 * m);
#pragma unroll
            for (int b = 0; b < 8; ++b) {
                ulonglong2 hv = *(const ulonglong2*)(hbp + b * HS + 32 * m);
#pragma unroll
                for (int g = 0; g < 3; ++g)
#pragma unroll
                    for (int jl = 0; jl < 2; ++jl) {
                        acc[g][jl][b] = ffma2(wv[g][jl].x, hv.x, acc[g][jl][b]);
                        acc[g][jl][b] = ffma2(wv[g][jl].y, hv.y, acc[g][jl][b]);
                    }
            }
        }

        float s0[3][2][8];
#pragma unroll
        for (int g = 0; g < 3; ++g)
#pragma unroll
            for (int jl = 0; jl < 2; ++jl)
#pragma unroll
                for (int b = 0; b < 8; ++b) {
                    float lo, hi; unpack2(acc[g][jl][b], lo, hi);
                    s0[g][jl][b] = lo + hi;
                }
        float s1[3][2][4];
#pragma unroll
        for (int g = 0; g < 3; ++g)
#pragma unroll
            for (int jl = 0; jl < 2; ++jl)
#pragma unroll
                for (int b = 0; b < 4; ++b) {
                    float e = s0[g][jl][2 * b], o = s0[g][jl][2 * b + 1];
                    float keep = k0 ? o : e, send = k0 ? e : o;
                    s1[g][jl][b] = keep + __shfl_xor_sync(0xffffffffu, send, 1);
                }
        float s2[3][2][2];
#pragma unroll
        for (int g = 0; g < 3; ++g)
#pragma unroll
            for (int jl = 0; jl < 2; ++jl)
#pragma unroll
                for (int b = 0; b < 2; ++b) {
                    float e = s1[g][jl][2 * b], o = s1[g][jl][2 * b + 1];
                    float keep = k1 ? o : e, send = k1 ? e : o;
                    s2[g][jl][b] = keep + __shfl_xor_sync(0xffffffffu, send, 2);
                }
        float sf[3][2];
#pragma unroll
        for (int g = 0; g < 3; ++g)
#pragma unroll
            for (int jl = 0; jl < 2; ++jl) {
                float e = s2[g][jl][0], o = s2[g][jl][1];
                float keep = k2 ? o : e, send = k2 ? e : o;
                sf[g][jl] = keep + __shfl_xor_sync(0xffffffffu, send, 4);
            }

        const float2 hold2 = *(const float2*)(h_buf + p * (8 * HS) + kc * HS + kglob);
        float r0 = sigm(gr2.x + bhr2.x + sf[0][0]);
        float z0 = sigm(gz2.x + bhz2.x + sf[1][0]);
        float n0 = tanh_e(fmaf(r0, sf[2][0] + bhn2.x, gn2.x));
        float hn0 = fmaf(z0, hold2.x - n0, n0);
        float r1 = sigm(gr2.y + bhr2.y + sf[0][1]);
        float z1 = sigm(gz2.y + bhz2.y + sf[1][1]);
        float n1 = tanh_e(fmaf(r1, sf[2][1] + bhn2.y, gn2.y));
        float hn1 = fmaf(z1, hold2.y - n1, n1);

        if (t == li)
            *(float2*)(out + (size_t)(b0 + kc) * 256 + kglob) = make_float2(hn0, hn1);

        int pn = p ^ 1;
        u64 hv2 = pack2(hn0, hn1);
        uint32_t off = (uint32_t)(((pn * 8 + kc) * HS + kglob) * 4);
#pragma unroll
        for (int q = 0; q < 4; ++q)
            asm volatile("st.shared::cluster.u64 [%0], %1;"
                         :: "r"(peer[q] + off), "l"(hv2) : "memory");

        asm volatile("barrier.cluster.arrive.aligned;" ::: "memory");
        gp += G3;
        if (t + 1 < Sdim) {
            gr2 = *(const float2*)(gp);
            gz2 = *(const float2*)(gp + 256);
            gn2 = *(const float2*)(gp + 512);
        }
        asm volatile("barrier.cluster.wait.aligned;" ::: "memory");
        p = pn;
    }
}

// ---------------------------------------------------------------------------
extern "C" void kernel_launch(void* const* d_in, const int* in_sizes, int n_in,
                              void* d_out, int out_size) {
    const float* tree  = (const float*)d_in[0];
    const float* seq   = (const float*)d_in[1];
    const int*   mask  = (const int*)  d_in[2];
    const float* W_ih  = (const float*)d_in[3];
    const float* W_hh  = (const float*)d_in[4];
    const float* b_ih  = (const float*)d_in[5];
    const float* b_hh  = (const float*)d_in[6];
    float* out = (float*)d_out;

    convert_w_kernel<<<G3, Hdim>>>(W_ih);
    dim3 gc(Bdim, Hdim / 32, Sdim / 64);
    convert_seq_kernel<<<gc, 256>>>(seq);

    cudaFuncSetAttribute(gi_mma_kernel,
                         cudaFuncAttributeMaxDynamicSharedMemorySize, GSM_TOTAL);
    dim3 g1((Bdim * Sdim) / 128, G3 / 128);
    gi_mma_kernel<<<g1, 256, GSM_TOTAL>>>(b_ih);

    cudaFuncSetAttribute(gru_rec_kernel,
                         cudaFuncAttributeMaxDynamicSharedMemorySize, RSM_BYTES);
    gru_rec_kernel<<<128, 256, RSM_BYTES>>>(tree, mask, W_hh, b_hh, out);
}

// round 10
// speedup vs baseline: 1.5469x; 1.0549x over previous
#include <cuda_runtime.h>
#include <cuda_bf16.h>
#include <mma.h>
#include <cstdint>

using namespace nvcuda;

#define Hdim 256
#define Sdim 512
#define Bdim 256
#define G3   768

// 402 MB scratch for precomputed input-gate activations gi[b*S + t][768]
__device__ float g_gi[(size_t)Bdim * Sdim * G3];

typedef unsigned long long u64;
__device__ __forceinline__ u64 pack2(float lo, float hi) {
    u64 r; asm("mov.b64 %0,{%1,%2};" : "=l"(r) : "f"(lo), "f"(hi)); return r;
}
__device__ __forceinline__ void unpack2(u64 v, float& lo, float& hi) {
    asm("mov.b64 {%0,%1},%2;" : "=f"(lo), "=f"(hi) : "l"(v));
}
__device__ __forceinline__ u64 ffma2(u64 a, u64 b, u64 c) {
    u64 d; asm("fma.rn.f32x2 %0,%1,%2,%3;" : "=l"(d) : "l"(a), "l"(b), "l"(c));
    return d;
}

// split float4 -> packed bf16x4 hi and lo (x = hi + lo)
__device__ __forceinline__ void cvt_split4(const float4 v, u64& hi_u, u64& lo_u) {
    __nv_bfloat16 h0 = __float2bfloat16(v.x), h1 = __float2bfloat16(v.y);
    __nv_bfloat16 h2 = __float2bfloat16(v.z), h3 = __float2bfloat16(v.w);
    float l0 = v.x - __bfloat162float(h0), l1 = v.y - __bfloat162float(h1);
    float l2 = v.z - __bfloat162float(h2), l3 = v.w - __bfloat162float(h3);
    union { __nv_bfloat162 b2[2]; u64 u; } uh, ul;
    uh.b2[0] = __nv_bfloat162(h0, h1); uh.b2[1] = __nv_bfloat162(h2, h3);
    ul.b2[0] = __nv_bfloat162(__float2bfloat16(l0), __float2bfloat16(l1));
    ul.b2[1] = __nv_bfloat162(__float2bfloat16(l2), __float2bfloat16(l3));
    hi_u = uh.u; lo_u = ul.u;
}

// ---------------------------------------------------------------------------
// Kernel 1: gi = x @ W_ih^T + b_ih, fused convert + bf16 WMMA (3-product split):
//   gi ~= Ah*Wh + Al*Wh + Ah*Wl   (fp32 accum)
// Reads seq / W_ih f32 directly; converts to bf16 hi/lo in-regs; A tile stored
// col-major [k][m] (natural from seq's t-contiguity), B tile [n][k].
// Global loads for kb+1 are register-prefetched under the mma block of kb.
// CTA 128x128, 8 warps (4m x 2n), warp tile 32x64 = 2x4 wmma 16x16x16.
// ---------------------------------------------------------------------------
#define AL  136                       // A tile ldm (m-stride padded)
#define LDB 40                        // B tile ldm
#define OF_AH 0
#define OF_AL 8704                    // 32*136*2
#define OF_BH 17408
#define OF_BL 27648                   // +128*40*2
#define OF_BIAS 37888
#define GSM_TOTAL (OF_BIAS + 16 * 128 * 4)   // 46,080 B

__global__ __launch_bounds__(256) void gi_mma_kernel(const float* __restrict__ seq,
                                                     const float* __restrict__ W_ih,
                                                     const float* __restrict__ b_ih) {
    extern __shared__ __align__(16) char smg[];
    __nv_bfloat16* As_h = (__nv_bfloat16*)(smg + OF_AH);
    __nv_bfloat16* As_l = (__nv_bfloat16*)(smg + OF_AL);
    __nv_bfloat16* Bs_h = (__nv_bfloat16*)(smg + OF_BH);
    __nv_bfloat16* Bs_l = (__nv_bfloat16*)(smg + OF_BL);
    float*         bias = (float*)(smg + OF_BIAS);

    const int tid = threadIdx.x;
    const int wid = tid >> 5;
    const int wm  = wid >> 1;         // warp rows [wm*32, +32)
    const int wn  = wid & 1;          // warp cols [wn*64, +64)
    const int b   = blockIdx.x >> 2;
    const int t0  = (blockIdx.x & 3) * 128;
    const int n0  = blockIdx.y * 128;
    const size_t mbase = (size_t)b * Sdim + t0;
    const float* seqb = seq + (size_t)b * (Hdim * Sdim);

    // per-thread load coordinates (4 A + 4 B float4s per kb)
    int akr[4], atc[4], brow[4], bg[4];
#pragma unroll
    for (int q = 0; q < 4; ++q) {
        int i = tid + q * 256;
        akr[q] = i >> 5;  atc[q] = i & 31;     // A: 32 k-rows x 32 float4 (t)
        brow[q] = i >> 3; bg[q] = i & 7;       // B: 128 n-rows x 8 float4 (k)
    }

    // bias broadcast tile: 16 identical rows of 128
    for (int i = tid; i < 16 * 128; i += 256) bias[i] = b_ih[n0 + (i & 127)];
    __syncthreads();

    wmma::fragment<wmma::accumulator, 16, 16, 16, float> c[2][4];
#pragma unroll
    for (int i = 0; i < 2; ++i)
#pragma unroll
        for (int j = 0; j < 4; ++j)
            wmma::load_matrix_sync(c[i][j], bias + wn * 64 + j * 16, 128,
                                   wmma::mem_row_major);

    float4 rA[4], rB[4];
#pragma unroll
    for (int q = 0; q < 4; ++q) {          // prefetch kb = 0
        rA[q] = *(const float4*)(seqb + (size_t)akr[q] * Sdim + t0 + atc[q] * 4);
        rB[q] = *(const float4*)(W_ih + (size_t)(n0 + brow[q]) * Hdim + bg[q] * 4);
    }

    for (int kb = 0; kb < 8; ++kb) {
        // convert regs -> smem bf16 hi/lo tiles
#pragma unroll
        for (int q = 0; q < 4; ++q) {
            u64 h, l;
            cvt_split4(rA[q], h, l);
            int so = akr[q] * AL + atc[q] * 4;   // [k][m]
            *(u64*)(As_h + so) = h;
            *(u64*)(As_l + so) = l;
            cvt_split4(rB[q], h, l);
            so = brow[q] * LDB + bg[q] * 4;      // [n][k]
            *(u64*)(Bs_h + so) = h;
            *(u64*)(Bs_l + so) = l;
        }
        __syncthreads();

        if (kb < 7) {                    // prefetch kb+1 under the mma block
            int ko = (kb + 1) * 32;
#pragma unroll
            for (int q = 0; q < 4; ++q) {
                rA[q] = *(const float4*)(seqb + (size_t)(ko + akr[q]) * Sdim + t0 + atc[q] * 4);
                rB[q] = *(const float4*)(W_ih + (size_t)(n0 + brow[q]) * Hdim + ko + bg[q] * 4);
            }
        }

#pragma unroll
        for (int ks = 0; ks < 2; ++ks) {
            wmma::fragment<wmma::matrix_a, 16, 16, 16, __nv_bfloat16, wmma::col_major> ah[2], al[2];
            wmma::fragment<wmma::matrix_b, 16, 16, 16, __nv_bfloat16, wmma::col_major> bh[4], bl[4];
#pragma unroll
            for (int i = 0; i < 2; ++i) {
                const __nv_bfloat16* pa = As_h + ks * 16 * AL + wm * 32 + i * 16;
                const __nv_bfloat16* qa = As_l + ks * 16 * AL + wm * 32 + i * 16;
                wmma::load_matrix_sync(ah[i], pa, AL);
                wmma::load_matrix_sync(al[i], qa, AL);
            }
#pragma unroll
            for (int j = 0; j < 4; ++j) {
                const __nv_bfloat16* pb = Bs_h + (wn * 64 + j * 16) * LDB + ks * 16;
                const __nv_bfloat16* qb = Bs_l + (wn * 64 + j * 16) * LDB + ks * 16;
                wmma::load_matrix_sync(bh[j], pb, LDB);
                wmma::load_matrix_sync(bl[j], qb, LDB);
            }
#pragma unroll
            for (int i = 0; i < 2; ++i)
#pragma unroll
                for (int j = 0; j < 4; ++j) {
                    wmma::mma_sync(c[i][j], ah[i], bh[j], c[i][j]);
                    wmma::mma_sync(c[i][j], al[i], bh[j], c[i][j]);
                    wmma::mma_sync(c[i][j], ah[i], bl[j], c[i][j]);
                }
        }
        __syncthreads();
    }

    // store to g_gi (row-major, ldm = G3)
#pragma unroll
    for (int i = 0; i < 2; ++i)
#pragma unroll
        for (int j = 0; j < 4; ++j) {
            float* dst = g_gi + (mbase + wm * 32 + i * 16) * G3 + n0 + wn * 64 + j * 16;
            wmma::store_matrix_sync(dst, c[i][j], G3, wmma::mem_row_major);
        }
}

// ---------------------------------------------------------------------------
// Kernel 2: persistent GRU recurrence v7 (unchanged — 1.61 ms measured).
// ---------------------------------------------------------------------------
#define WS 264
#define HS 260
#define WS_FLOATS (192 * WS)
#define HB_FLOATS (2 * 8 * HS)
#define RSM_BYTES ((WS_FLOATS + HB_FLOATS + 8) * 4)

__device__ __forceinline__ float sigm(float x) {
    return __fdividef(1.f, 1.f + __expf(-x));
}
__device__ __forceinline__ float tanh_e(float x) {
    return __fdividef(2.f, 1.f + __expf(-2.f * x)) - 1.f;
}

__global__ __launch_bounds__(256, 1) __cluster_dims__(4, 1, 1)
void gru_rec_kernel(const float* __restrict__ tree,
                    const int*   __restrict__ mask,
                    const float* __restrict__ W_hh,
                    const float* __restrict__ b_hh,
                    float*       __restrict__ out) {
    extern __shared__ __align__(16) float sm[];
    float* W_s   = sm;
    float* h_buf = sm + WS_FLOATS;
    int*   li_s  = (int*)(h_buf + HB_FLOATS);

    const int tid = threadIdx.x;
    const int r   = blockIdx.x & 3;
    const int b0  = (blockIdx.x >> 2) * 8;

    for (int i = tid; i < 192 * 256; i += 256) {
        int row = i >> 8, k = i & 255;
        int grow = (row >> 6) * 256 + r * 64 + (row & 63);
        W_s[row * WS + k] = W_hh[(size_t)grow * 256 + k];
    }
    for (int i = tid; i < 8 * 256; i += 256)
        h_buf[(i >> 8) * HS + (i & 255)] = tree[(size_t)b0 * 256 + i];
    {
        int bb = tid >> 5, ln = tid & 31;
        int s = 0;
        for (int i = ln; i < 512; i += 32) s += mask[(size_t)(b0 + bb) * 512 + i];
#pragma unroll
        for (int o = 16; o; o >>= 1) s += __shfl_xor_sync(0xffffffffu, s, o);
        if (ln == 0) li_s[bb] = (s > 0) ? (s - 1) : 0;
    }
    __syncthreads();
    asm volatile("barrier.cluster.arrive.aligned;" ::: "memory");
    asm volatile("barrier.cluster.wait.aligned;" ::: "memory");

    const int lane = tid & 31;
    const int w    = tid >> 5;
    const int kc   = lane & 7;
    const int jg   = w * 4 + (lane >> 3);
    const int kglob = r * 64 + jg * 2;

    const float* wb[3][2];
#pragma unroll
    for (int g = 0; g < 3; ++g)
#pragma unroll
        for (int jl = 0; jl < 2; ++jl)
            wb[g][jl] = W_s + (g * 64 + jg * 2 + jl) * WS + kc * 4;

    const float2 bhr2 = *(const float2*)(b_hh + kglob);
    const float2 bhz2 = *(const float2*)(b_hh + 256 + kglob);
    const float2 bhn2 = *(const float2*)(b_hh + 512 + kglob);
    const int li = li_s[kc];

    uint32_t hb_u32;
    asm("{ .reg .u64 t0; cvta.to.shared.u64 t0, %1; cvt.u32.u64 %0, t0; }"
        : "=r"(hb_u32) : "l"(h_buf));
    uint32_t peer[4];
#pragma unroll
    for (int q = 0; q < 4; ++q)
        asm("mapa.shared::cluster.u32 %0, %1, %2;" : "=r"(peer[q]) : "r"(hb_u32), "r"(q));

    const float* gp = g_gi + ((size_t)(b0 + kc) * Sdim) * G3 + kglob;
    float2 gr2 = *(const float2*)(gp);
    float2 gz2 = *(const float2*)(gp + 256);
    float2 gn2 = *(const float2*)(gp + 512);

    const int k0 = kc & 1, k1 = (kc >> 1) & 1, k2 = (kc >> 2) & 1;

    int p = 0;
    for (int t = 0; t < Sdim; ++t) {
        const float* hbp = h_buf + p * (8 * HS) + kc * 4;
        u64 acc[3][2][8];
#pragma unroll
        for (int g = 0; g < 3; ++g)
#pragma unroll
            for (int jl = 0; jl < 2; ++jl)
#pragma unroll
                for (int b = 0; b < 8; ++b) acc[g][jl][b] = 0ull;

#pragma unroll
        for (int m = 0; m < 8; ++m) {
            ulonglong2 wv[3][2];
#pragma unroll
            for (int g = 0; g < 3; ++g)
#pragma unroll
                for (int jl = 0; jl < 2; ++jl)
                    wv[g][jl] = *(const ulonglong2*)(wb[g][jl] + 32 * m);
#pragma unroll
            for (int b = 0; b < 8; ++b) {
                ulonglong2 hv = *(const ulonglong2*)(hbp + b * HS + 32 * m);
#pragma unroll
                for (int g = 0; g < 3; ++g)
#pragma unroll
                    for (int jl = 0; jl < 2; ++jl) {
                        acc[g][jl][b] = ffma2(wv[g][jl].x, hv.x, acc[g][jl][b]);
                        acc[g][jl][b] = ffma2(wv[g][jl].y, hv.y, acc[g][jl][b]);
                    }
            }
        }

        float s0[3][2][8];
#pragma unroll
        for (int g = 0; g < 3; ++g)
#pragma unroll
            for (int jl = 0; jl < 2; ++jl)
#pragma unroll
                for (int b = 0; b < 8; ++b) {
                    float lo, hi; unpack2(acc[g][jl][b], lo, hi);
                    s0[g][jl][b] = lo + hi;
                }
        float s1[3][2][4];
#pragma unroll
        for (int g = 0; g < 3; ++g)
#pragma unroll
            for (int jl = 0; jl < 2; ++jl)
#pragma unroll
                for (int b = 0; b < 4; ++b) {
                    float e = s0[g][jl][2 * b], o = s0[g][jl][2 * b + 1];
                    float keep = k0 ? o : e, send = k0 ? e : o;
                    s1[g][jl][b] = keep + __shfl_xor_sync(0xffffffffu, send, 1);
                }
        float s2[3][2][2];
#pragma unroll
        for (int g = 0; g < 3; ++g)
#pragma unroll
            for (int jl = 0; jl < 2; ++jl)
#pragma unroll
                for (int b = 0; b < 2; ++b) {
                    float e = s1[g][jl][2 * b], o = s1[g][jl][2 * b + 1];
                    float keep = k1 ? o : e, send = k1 ? e : o;
                    s2[g][jl][b] = keep + __shfl_xor_sync(0xffffffffu, send, 2);
                }
        float sf[3][2];
#pragma unroll
        for (int g = 0; g < 3; ++g)
#pragma unroll
            for (int jl = 0; jl < 2; ++jl) {
                float e = s2[g][jl][0], o = s2[g][jl][1];
                float keep = k2 ? o : e, send = k2 ? e : o;
                sf[g][jl] = keep + __shfl_xor_sync(0xffffffffu, send, 4);
            }

        const float2 hold2 = *(const float2*)(h_buf + p * (8 * HS) + kc * HS + kglob);
        float r0 = sigm(gr2.x + bhr2.x + sf[0][0]);
        float z0 = sigm(gz2.x + bhz2.x + sf[1][0]);
        float n0 = tanh_e(fmaf(r0, sf[2][0] + bhn2.x, gn2.x));
        float hn0 = fmaf(z0, hold2.x - n0, n0);
        float r1 = sigm(gr2.y + bhr2.y + sf[0][1]);
        float z1 = sigm(gz2.y + bhz2.y + sf[1][1]);
        float n1 = tanh_e(fmaf(r1, sf[2][1] + bhn2.y, gn2.y));
        float hn1 = fmaf(z1, hold2.y - n1, n1);

        if (t == li)
            *(float2*)(out + (size_t)(b0 + kc) * 256 + kglob) = make_float2(hn0, hn1);

        int pn = p ^ 1;
        u64 hv2 = pack2(hn0, hn1);
        uint32_t off = (uint32_t)(((pn * 8 + kc) * HS + kglob) * 4);
#pragma unroll
        for (int q = 0; q < 4; ++q)
            asm volatile("st.shared::cluster.u64 [%0], %1;"
                         :: "r"(peer[q] + off), "l"(hv2) : "memory");

        asm volatile("barrier.cluster.arrive.aligned;" ::: "memory");
        gp += G3;
        if (t + 1 < Sdim) {
            gr2 = *(const float2*)(gp);
            gz2 = *(const float2*)(gp + 256);
            gn2 = *(const float2*)(gp + 512);
        }
        asm volatile("barrier.cluster.wait.aligned;" ::: "memory");
        p = pn;
    }
}

// ---------------------------------------------------------------------------
extern "C" void kernel_launch(void* const* d_in, const int* in_sizes, int n_in,
                              void* d_out, int out_size) {
    const float* tree  = (const float*)d_in[0];
    const float* seq   = (const float*)d_in[1];
    const int*   mask  = (const int*)  d_in[2];
    const float* W_ih  = (const float*)d_in[3];
    const float* W_hh  = (const float*)d_in[4];
    const float* b_ih  = (const float*)d_in[5];
    const float* b_hh  = (const float*)d_in[6];
    float* out = (float*)d_out;

    cudaFuncSetAttribute(gi_mma_kernel,
                         cudaFuncAttributeMaxDynamicSharedMemorySize, GSM_TOTAL);
    dim3 g1((Bdim * Sdim) / 128, G3 / 128);
    gi_mma_kernel<<<g1, 256, GSM_TOTAL>>>(seq, W_ih, b_ih);

    cudaFuncSetAttribute(gru_rec_kernel,
                         cudaFuncAttributeMaxDynamicSharedMemorySize, RSM_BYTES);
    gru_rec_kernel<<<128, 256, RSM_BYTES>>>(tree, mask, W_hh, b_hh, out);
}